// round 10
// baseline (speedup 1.0000x reference)
#include <cuda_runtime.h>
#include <math.h>
#include <limits.h>

// Problem constants: B=4096, DIM=512, C=128, TEMP=0.05
#define MAXB 8192
#define MAXC 128
#define DIM  512

__device__ int   g_hcnt[MAXC];       // zero at load; scan_kernel re-zeros each replay
__device__ int   g_scat[MAXC];
__device__ int   g_lab[MAXB];
__device__ int   g_bstart[MAXC + 1];
__device__ int   g_bidx[MAXB];
__device__ float g_norm[MAXB];
__device__ float g_sum;
__device__ float g_cnt;
__device__ int   g_done;

__device__ __forceinline__ float warp_sum(float v)
{
    #pragma unroll
    for (int o = 16; o > 0; o >>= 1)
        v += __shfl_xor_sync(0xFFFFFFFFu, v, o);
    return v;
}

// ---------------------------------------------------------------------------
// K1: histogram (smem + global merge) + row norms (warp-per-row). Wide grid.
// ---------------------------------------------------------------------------
__global__ void __launch_bounds__(256)
hist_norm_kernel(const int* __restrict__ labels,
                 const float* __restrict__ batch, int n)
{
    __shared__ int s_h[MAXC];
    int tid = threadIdx.x;
    for (int c = tid; c < MAXC; c += 256) s_h[c] = 0;
    __syncthreads();

    int gsz = gridDim.x * 256;
    for (int i = blockIdx.x * 256 + tid; i < n; i += gsz) {
        int l = labels[i];
        l = (l < 0) ? 0 : (l >= MAXC ? MAXC - 1 : l);
        g_lab[i] = l;
        atomicAdd(&s_h[l], 1);
    }
    __syncthreads();
    for (int c = tid; c < MAXC; c += 256) {
        int v = s_h[c];
        if (v) atomicAdd(&g_hcnt[c], v);
    }

    // norms (also warms L2 with the batch)
    int nwarp = gsz >> 5;
    int gw    = (blockIdx.x * 256 + tid) >> 5;
    int lane  = tid & 31;
    for (int r = gw; r < n; r += nwarp) {
        const float4* rp = (const float4*)(batch + (size_t)r * DIM);
        float a = 0.f, b = 0.f;
        #pragma unroll
        for (int q = 0; q < 4; q++) {
            float4 v = rp[lane + 32 * q];
            a = fmaf(v.x, v.x, a); b = fmaf(v.y, v.y, b);
            a = fmaf(v.z, v.z, a); b = fmaf(v.w, v.w, b);
        }
        float s = warp_sum(a + b);
        if (lane == 0) g_norm[r] = s;
    }
}

// ---------------------------------------------------------------------------
// K2: 128-thread scan over bins; init scatter cursors; reset replay state.
// ---------------------------------------------------------------------------
__global__ void __launch_bounds__(MAXC)
scan_kernel()
{
    __shared__ int s_wsum[4];
    int tid  = threadIdx.x;       // 0..127 == bin
    int lane = tid & 31, w = tid >> 5;
    int cnt  = g_hcnt[tid];
    int x    = cnt;
    #pragma unroll
    for (int o = 1; o < 32; o <<= 1) {
        int y = __shfl_up_sync(0xFFFFFFFFu, x, o);
        if (lane >= o) x += y;
    }
    if (lane == 31) s_wsum[w] = x;
    __syncthreads();
    int add = 0;
    #pragma unroll
    for (int k = 0; k < 4; k++) add += (k < w) ? s_wsum[k] : 0;
    int incl = x + add;
    int excl = incl - cnt;
    g_bstart[tid] = excl;
    g_scat[tid]   = excl;
    if (tid == MAXC - 1) g_bstart[MAXC] = incl;
    g_hcnt[tid] = 0;                          // ready for next graph replay
    if (tid == 0) { g_sum = 0.f; g_cnt = 0.f; g_done = 0; }
}

// ---------------------------------------------------------------------------
// K3: scatter indices into buckets. Wide grid. (In-bucket order irrelevant:
//     argmin tie-break compares row indices j, not slot positions.)
// ---------------------------------------------------------------------------
__global__ void __launch_bounds__(256)
scatter_kernel(int n)
{
    int gsz = gridDim.x * 256;
    for (int i = blockIdx.x * 256 + threadIdx.x; i < n; i += gsz) {
        int l = g_lab[i];
        int p = atomicAdd(&g_scat[l], 1);
        g_bidx[p] = i;
    }
}

// ---------------------------------------------------------------------------
// direct squared distance (warp-cooperative, matches reference _pair_dist)
// ---------------------------------------------------------------------------
__device__ __forceinline__ float direct_d2(const float* __restrict__ batch,
                                           int a, int b, int lane)
{
    const float4* ra = (const float4*)(batch + (size_t)a * DIM);
    const float4* rb = (const float4*)(batch + (size_t)b * DIM);
    float c0 = 0.f, c1 = 0.f;
    #pragma unroll
    for (int q = 0; q < 4; q++) {
        float4 x = ra[lane + 32 * q];
        float4 y = rb[lane + 32 * q];
        float d;
        d = x.x - y.x; c0 = fmaf(d, d, c0);
        d = x.y - y.y; c1 = fmaf(d, d, c1);
        d = x.z - y.z; c0 = fmaf(d, d, c0);
        d = x.w - y.w; c1 = fmaf(d, d, c1);
    }
    return warp_sum(c0 + c1);
}

__device__ __forceinline__ void loss_term(const float* batch, int t, int bj,
                                          const int* anchors, const int* negatives,
                                          int lane, float* s_sum, int* s_cnt2)
{
    int a  = anchors[t];
    int ng = negatives[t];
    float dap2 = direct_d2(batch, a, bj, lane);
    float dan2 = direct_d2(batch, a, ng, lane);
    if (lane == 0) {
        float d_ap = sqrtf(fmaxf(dap2, 1e-12f));
        float d_an = sqrtf(fmaxf(dan2, 1e-12f));
        float z    = (d_ap - d_an) * 10.0f;    // (s_an - s_ap)/0.05
        float per  = fmaxf(z, 0.f) + log1pf(expf(-fabsf(z)));
        atomicAdd(s_sum, per);
        atomicAdd(s_cnt2, 1);
    }
}

// ---------------------------------------------------------------------------
// K4: one warp per TWO consecutive anchor slots (shared candidate loads).
// ---------------------------------------------------------------------------
__global__ void __launch_bounds__(128)
triplet_kernel(const float* __restrict__ batch,
               const int* __restrict__ anchors,
               const int* __restrict__ negatives,
               int n, float* __restrict__ out)
{
    __shared__ float s_sum;
    __shared__ int   s_cnt2;
    int w    = threadIdx.x >> 5;
    int lane = threadIdx.x & 31;
    int gw   = blockIdx.x * 4 + w;
    int slotA = 2 * gw;
    int slotB = 2 * gw + 1;

    if (threadIdx.x == 0) { s_sum = 0.f; s_cnt2 = 0; }

    bool hasA = slotA < n;
    bool hasB = slotB < n;

    if (hasA) {
        int tA = g_bidx[slotA];
        int tB = g_bidx[hasB ? slotB : slotA];
        int labA = g_lab[tA], labB = g_lab[tB];
        int sA = g_bstart[labA], eA = g_bstart[labA + 1];
        int sB = g_bstart[labB], eB = g_bstart[labB + 1];
        if (!hasB) { sB = eA; eB = eA; }     // empty window for B

        const float4* rA = (const float4*)(batch + (size_t)tA * DIM);
        const float4* rB = (const float4*)(batch + (size_t)tB * DIM);
        float4 xa0 = rA[lane],      xa1 = rA[lane + 32];
        float4 xa2 = rA[lane + 64], xa3 = rA[lane + 96];
        float4 xb0 = rB[lane],      xb1 = rB[lane + 32];
        float4 xb2 = rB[lane + 64], xb3 = rB[lane + 96];

        float bestA = INFINITY, bestB = INFINITY;
        int   bjA = INT_MAX,    bjB = INT_MAX;

        // combined contiguous range [sA, eB); per-anchor windows predicated
        for (int p = sA; p < eB; p += 2) {
            bool v1 = (p + 1) < eB;
            int j0 = g_bidx[p];
            int j1 = g_bidx[v1 ? p + 1 : p];
            float n0 = g_norm[j0];
            float n1 = g_norm[j1];
            const float4* r0 = (const float4*)(batch + (size_t)j0 * DIM);
            const float4* r1 = (const float4*)(batch + (size_t)j1 * DIM);

            float dA0 = 0.f, dA1 = 0.f, dB0 = 0.f, dB1 = 0.f;
            #pragma unroll
            for (int q = 0; q < 4; q++) {
                float4 xA = (q==0)?xa0:(q==1)?xa1:(q==2)?xa2:xa3;
                float4 xB = (q==0)?xb0:(q==1)?xb1:(q==2)?xb2:xb3;
                float4 y0 = r0[lane + 32 * q];
                float4 y1 = r1[lane + 32 * q];
                dA0 = fmaf(xA.x, y0.x, dA0); dA0 = fmaf(xA.y, y0.y, dA0);
                dA0 = fmaf(xA.z, y0.z, dA0); dA0 = fmaf(xA.w, y0.w, dA0);
                dA1 = fmaf(xA.x, y1.x, dA1); dA1 = fmaf(xA.y, y1.y, dA1);
                dA1 = fmaf(xA.z, y1.z, dA1); dA1 = fmaf(xA.w, y1.w, dA1);
                dB0 = fmaf(xB.x, y0.x, dB0); dB0 = fmaf(xB.y, y0.y, dB0);
                dB0 = fmaf(xB.z, y0.z, dB0); dB0 = fmaf(xB.w, y0.w, dB0);
                dB1 = fmaf(xB.x, y1.x, dB1); dB1 = fmaf(xB.y, y1.y, dB1);
                dB1 = fmaf(xB.z, y1.z, dB1); dB1 = fmaf(xB.w, y1.w, dB1);
            }
            #pragma unroll
            for (int o = 16; o > 0; o >>= 1) {
                dA0 += __shfl_xor_sync(0xFFFFFFFFu, dA0, o);
                dA1 += __shfl_xor_sync(0xFFFFFFFFu, dA1, o);
                dB0 += __shfl_xor_sync(0xFFFFFFFFu, dB0, o);
                dB1 += __shfl_xor_sync(0xFFFFFFFFu, dB1, o);
            }
            float mA0 = fmaf(-2.f, dA0, n0);
            float mA1 = fmaf(-2.f, dA1, n1);
            float mB0 = fmaf(-2.f, dB0, n0);
            float mB1 = fmaf(-2.f, dB1, n1);

            if (p < eA && j0 != tA &&
                (mA0 < bestA || (mA0 == bestA && j0 < bjA))) { bestA = mA0; bjA = j0; }
            if (v1 && (p + 1) < eA && j1 != tA &&
                (mA1 < bestA || (mA1 == bestA && j1 < bjA))) { bestA = mA1; bjA = j1; }
            if (p >= sB && j0 != tB &&
                (mB0 < bestB || (mB0 == bestB && j0 < bjB))) { bestB = mB0; bjB = j0; }
            if (v1 && (p + 1) >= sB && j1 != tB &&
                (mB1 < bestB || (mB1 == bestB && j1 < bjB))) { bestB = mB1; bjB = j1; }
        }

        if ((eA - sA) > 2)
            loss_term(batch, tA, bjA, anchors, negatives, lane, &s_sum, &s_cnt2);
        if (hasB && (eB - sB) > 2)
            loss_term(batch, tB, bjB, anchors, negatives, lane, &s_sum, &s_cnt2);
    }

    __syncthreads();
    if (threadIdx.x == 0) {
        if (s_cnt2 > 0) {
            atomicAdd(&g_sum, s_sum);
            atomicAdd(&g_cnt, (float)s_cnt2);
        }
        __threadfence();
        int done = atomicAdd(&g_done, 1);
        if (done == (int)gridDim.x - 1) {
            float sum = atomicAdd(&g_sum, 0.0f);
            float cn  = atomicAdd(&g_cnt, 0.0f);
            out[0] = sum / cn;
        }
    }
}

// ---------------------------------------------------------------------------
extern "C" void kernel_launch(void* const* d_in, const int* in_sizes, int n_in,
                              void* d_out, int out_size)
{
    const float* batch     = (const float*)d_in[0];
    const int*   labels    = (const int*)d_in[1];
    const int*   anchors   = (const int*)d_in[2];
    const int*   negatives = (const int*)d_in[3];
    float*       out       = (float*)d_out;

    int n = in_sizes[1];

    hist_norm_kernel<<<64, 256>>>(labels, batch, n);
    scan_kernel<<<1, MAXC>>>();
    scatter_kernel<<<16, 256>>>(n);

    int pairs  = (n + 1) / 2;                 // 2 anchors per warp
    int blocks = (pairs + 3) / 4;             // 4 warps per block
    triplet_kernel<<<blocks, 128>>>(batch, anchors, negatives, n, out);
}